// round 7
// baseline (speedup 1.0000x reference)
#include <cuda_runtime.h>
#include <cstdint>

// Fused SimpleCNN forward (kmeans path = 1e-5 blend -> dropped; fold pipeline
// == plain 3x3 pad-1 conv).
//
// R7: R4 skeleton (2 CTAs/image + separate reduce kernel) with stage-2
// de-bottlenecked: h1p stored as pre-broadcast u64 pairs (no dependent movs),
// weights vectorized via LDS.128 (ulonglong2), hand-packed SMEM arena.

__device__ __forceinline__ uint64_t fma2(uint64_t a, uint64_t b, uint64_t c) {
    uint64_t d;
    asm("fma.rn.f32x2 %0, %1, %2, %3;" : "=l"(d) : "l"(a), "l"(b), "l"(c));
    return d;
}
__device__ __forceinline__ uint64_t bcast2(float v) {
    uint64_t d; asm("mov.b64 %0, {%1, %1};" : "=l"(d) : "f"(v)); return d;
}
__device__ __forceinline__ uint64_t pack2(float lo, float hi) {
    uint64_t d; asm("mov.b64 %0, {%1, %2};" : "=l"(d) : "f"(lo), "f"(hi)); return d;
}
__device__ __forceinline__ void unpack2(uint64_t v, float& lo, float& hi) {
    asm("mov.b64 {%0, %1}, %2;" : "=f"(lo), "=f"(hi) : "l"(v));
}

#define THREADS 512

__device__ float g_partial[256 * 10];   // [img*2+half][10] FC partials

// SMEM arena layout (bytes):
//   h1p  u64[16][16][17]   @     0  (34816)  pooled L1, pre-broadcast pairs
//   w2p  u64[8][16][10]    @ 34816  (10240)  conv2 weights, oc-pair packed, k-padded
//   xs   f32[840]          @ 45056  ( 3360)  28x30 col-padded input; aliased by h2s[784]
//   w1p  u64[9*8]          @ 48416  (  576)  [k*8+pp]
//   b1p  u64[8]            @ 48992  (   64)
//   b2p  u64[8]            @ 49056  (   64)
// total 49120 <= 49152
#define OFF_H1P 0
#define OFF_W2P 34816
#define OFF_XS  45056
#define OFF_W1P 48416
#define OFF_B1P 48992
#define OFF_B2P 49056

__global__ __launch_bounds__(THREADS, 2) void fused_cnn_kernel(
    const float* __restrict__ x,     // [B,1,28,28]
    const float* __restrict__ w1,    // [16,1,3,3]
    const float* __restrict__ b1,    // [16]
    const float* __restrict__ w2,    // [32,16,3,3]
    const float* __restrict__ b2,    // [32]
    const float* __restrict__ fcw)   // [10,1568]
{
    __shared__ __align__(16) unsigned char smraw[49120];
    uint64_t* h1p = reinterpret_cast<uint64_t*>(smraw + OFF_H1P);   // [(ic*16+r)*17 + c]
    uint64_t* w2p = reinterpret_cast<uint64_t*>(smraw + OFF_W2P);   // [(pp*16+ic)*10 + k]
    float*    xs  = reinterpret_cast<float*>(smraw + OFF_XS);       // [r*30 + c], r<28
    float*    h2s = xs;                                             // alias (stage2+)
    uint64_t* w1p = reinterpret_cast<uint64_t*>(smraw + OFF_W1P);
    uint64_t* b1p = reinterpret_cast<uint64_t*>(smraw + OFF_B1P);
    uint64_t* b2p = reinterpret_cast<uint64_t*>(smraw + OFF_B2P);

    const int b    = blockIdx.x >> 1;       // image
    const int half = blockIdx.x & 1;        // 0: ocs 0-15, 1: ocs 16-31
    const int tid  = threadIdx.x;
    const float* xb = x + b * 784;

    // ---- Stage 0: stage input (col-padded) + pack weights + zero h1p ----
    for (int i = tid; i < 840; i += THREADS) {
        int r = i / 30, c = i % 30;
        xs[i] = (c >= 1 && c <= 28) ? xb[r * 28 + (c - 1)] : 0.f;
    }
    for (int i = tid; i < 4352; i += THREADS) h1p[i] = 0ull;
    for (int i = tid; i < 1152; i += THREADS) {
        int pp = i / 144, r = i % 144, ic = r / 9, k = r % 9;
        int oc = half * 16 + 2 * pp;
        w2p[(pp * 16 + ic) * 10 + k] = pack2(w2[oc * 144 + ic * 9 + k],
                                             w2[(oc + 1) * 144 + ic * 9 + k]);
    }
    if (tid < 72) {
        int k = tid / 8, pp = tid % 8;
        w1p[k * 8 + pp] = pack2(w1[(2 * pp) * 9 + k], w1[(2 * pp + 1) * 9 + k]);
    }
    if (tid < 8) {
        b1p[tid] = pack2(b1[2 * tid], b1[2 * tid + 1]);
        b2p[tid] = pack2(b2[half * 16 + 2 * tid], b2[half * 16 + 2 * tid + 1]);
    }
    __syncthreads();

    // ---- Stage 1: conv1 + relu + pool2 -> h1p (pre-broadcast u64 pairs) ----
    // 392 threads: gg = tid/196 -> pairs gg*4..gg*4+3; pos = tid%196.
    if (tid < 392) {
        const int gg  = tid / 196;
        const int pos = tid % 196;
        const int ph = pos / 14, pw = pos % 14;
        const int h = 2 * ph, w = 2 * pw;   // padded coords; window rows h..h+3

        uint64_t winb[16];
        #pragma unroll
        for (int r = 0; r < 4; r++) {
            const int orow = h + r - 1;     // original row (-1..28)
            if (orow >= 0 && orow < 28) {   // warp-uniform branch (lanes share ph)
                const float2* row = reinterpret_cast<const float2*>(&xs[orow * 30 + w]);
                float2 a = row[0], c = row[1];
                winb[r * 4 + 0] = bcast2(a.x); winb[r * 4 + 1] = bcast2(a.y);
                winb[r * 4 + 2] = bcast2(c.x); winb[r * 4 + 3] = bcast2(c.y);
            } else {
                winb[r * 4 + 0] = 0ull; winb[r * 4 + 1] = 0ull;
                winb[r * 4 + 2] = 0ull; winb[r * 4 + 3] = 0ull;
            }
        }

        #pragma unroll
        for (int q = 0; q < 4; q++) {
            const int pp = gg * 4 + q;
            uint64_t wk[9];
            #pragma unroll
            for (int k = 0; k < 9; k++) wk[k] = w1p[k * 8 + pp];
            uint64_t acc[4];
            #pragma unroll
            for (int p = 0; p < 4; p++) acc[p] = b1p[pp];
            #pragma unroll
            for (int p = 0; p < 4; p++) {
                const int dy = p >> 1, dx = p & 1;
                #pragma unroll
                for (int kh = 0; kh < 3; kh++)
                    #pragma unroll
                    for (int kw = 0; kw < 3; kw++)
                        acc[p] = fma2(winb[(dy + kh) * 4 + (dx + kw)],
                                      wk[kh * 3 + kw], acc[p]);
            }
            float l0, h0, l1, h1, l2, h2, l3, h3;
            unpack2(acc[0], l0, h0); unpack2(acc[1], l1, h1);
            unpack2(acc[2], l2, h2); unpack2(acc[3], l3, h3);
            float mlo = fmaxf(fmaxf(fmaxf(l0, l1), fmaxf(l2, l3)), 0.f);
            float mhi = fmaxf(fmaxf(fmaxf(h0, h1), fmaxf(h2, h3)), 0.f);
            h1p[((2 * pp) * 16 + ph + 1) * 17 + (pw + 1)]     = bcast2(mlo);
            h1p[((2 * pp + 1) * 16 + ph + 1) * 17 + (pw + 1)] = bcast2(mhi);
        }
    }
    __syncthreads();

    // ---- Stage 2: conv2 (16 -> this CTA's 16 ocs) + relu + pool2 -> h2s ----
    // 196 threads: g2 = tid/49 -> local pairs 2g2, 2g2+1; pos = tid%49.
    // Window loads are direct u64 (pre-broadcast); weights via LDS.128.
    if (tid < 196) {
        const int g2  = tid / 49;
        const int pos = tid % 49;
        const int ph = pos / 7, pw = pos % 7;
        const int h = 2 * ph, w = 2 * pw;

        uint64_t acc[2][4];
        #pragma unroll
        for (int q = 0; q < 2; q++)
            #pragma unroll
            for (int p = 0; p < 4; p++) acc[q][p] = b2p[2 * g2 + q];

        for (int ic = 0; ic < 16; ic++) {
            uint64_t winb[16];
            #pragma unroll
            for (int r = 0; r < 4; r++) {
                const uint64_t* row = &h1p[(ic * 16 + h + r) * 17 + w];
                winb[r * 4 + 0] = row[0]; winb[r * 4 + 1] = row[1];
                winb[r * 4 + 2] = row[2]; winb[r * 4 + 3] = row[3];
            }
            #pragma unroll
            for (int q = 0; q < 2; q++) {
                const int pp = 2 * g2 + q;
                const uint64_t* wp = &w2p[(pp * 16 + ic) * 10];
                ulonglong2 w01 = *reinterpret_cast<const ulonglong2*>(wp);
                ulonglong2 w23 = *reinterpret_cast<const ulonglong2*>(wp + 2);
                ulonglong2 w45 = *reinterpret_cast<const ulonglong2*>(wp + 4);
                ulonglong2 w67 = *reinterpret_cast<const ulonglong2*>(wp + 6);
                uint64_t wk8 = wp[8];
                uint64_t wk[9] = { w01.x, w01.y, w23.x, w23.y,
                                   w45.x, w45.y, w67.x, w67.y, wk8 };
                #pragma unroll
                for (int p = 0; p < 4; p++) {
                    const int dy = p >> 1, dx = p & 1;
                    #pragma unroll
                    for (int kh = 0; kh < 3; kh++)
                        #pragma unroll
                        for (int kw = 0; kw < 3; kw++)
                            acc[q][p] = fma2(winb[(dy + kh) * 4 + (dx + kw)],
                                             wk[kh * 3 + kw], acc[q][p]);
                }
            }
        }

        #pragma unroll
        for (int q = 0; q < 2; q++) {
            float l0, h0, l1, h1, l2, h2, l3, h3;
            unpack2(acc[q][0], l0, h0); unpack2(acc[q][1], l1, h1);
            unpack2(acc[q][2], l2, h2); unpack2(acc[q][3], l3, h3);
            float mlo = fmaxf(fmaxf(fmaxf(l0, l1), fmaxf(l2, l3)), 0.f);
            float mhi = fmaxf(fmaxf(fmaxf(h0, h1), fmaxf(h2, h3)), 0.f);
            const int loc = 2 * (2 * g2 + q);
            h2s[loc * 49 + pos]       = mlo;
            h2s[(loc + 1) * 49 + pos] = mhi;
        }
    }
    __syncthreads();

    // ---- Stage 3: partial FC over this CTA's 784 features (one warp per output) ----
    if (tid < 320) {
        const int o = tid >> 5, l = tid & 31;
        const float* wrow = fcw + o * 1568 + half * 784;
        float s = 0.f;
        #pragma unroll
        for (int k = l; k < 784; k += 32)
            s += h2s[k] * wrow[k];
        #pragma unroll
        for (int off = 16; off; off >>= 1)
            s += __shfl_xor_sync(0xffffffffu, s, off);
        if (l == 0) g_partial[blockIdx.x * 10 + o] = s;
    }
}

__global__ void reduce_fc_kernel(const float* __restrict__ fcb,
                                 float* __restrict__ out)
{
    int i = blockIdx.x * blockDim.x + threadIdx.x;
    if (i < 1280) {
        int img = i / 10, o = i % 10;
        out[i] = g_partial[(img * 2) * 10 + o] + g_partial[(img * 2 + 1) * 10 + o] + fcb[o];
    }
}

extern "C" void kernel_launch(void* const* d_in, const int* in_sizes, int n_in,
                              void* d_out, int out_size) {
    const float* x   = (const float*)d_in[0];
    const float* w1  = (const float*)d_in[1];
    const float* b1  = (const float*)d_in[2];
    const float* w2  = (const float*)d_in[3];
    const float* b2  = (const float*)d_in[4];
    const float* fcw = (const float*)d_in[5];
    const float* fcb = (const float*)d_in[6];
    float* out = (float*)d_out;

    const int B = in_sizes[0] / 784;  // 128
    fused_cnn_kernel<<<B * 2, THREADS>>>(x, w1, b1, w2, b2, fcw);
    reduce_fc_kernel<<<10, 128>>>(fcb, out);
}

// round 9
// speedup vs baseline: 1.0967x; 1.0967x over previous
#include <cuda_runtime.h>
#include <cstdint>

// Fused SimpleCNN forward (kmeans path = 1e-5 blend -> dropped; fold pipeline
// == plain 3x3 pad-1 conv).
//
// R9 == R8 resubmit (R8 hit a broker/container infra failure; kernel never ran).
// Single kernel, 1 CTA per image (128 CTAs = 1/SM, single wave).
// Conv2+pool2 via Winograd F(2x2,3x3): each 4x4 input tile -> 2x2 conv outputs
// = exactly one maxpool window -> one pooled value. 2.25x MAC reduction on the
// binding fma pipe. lane==oc mapping: transformed tiles broadcast via LDS,
// weights pre-transformed (G w G^T) into SMEM as k-pair packed u64.

__device__ __forceinline__ uint64_t fma2(uint64_t a, uint64_t b, uint64_t c) {
    uint64_t d;
    asm("fma.rn.f32x2 %0, %1, %2, %3;" : "=l"(d) : "l"(a), "l"(b), "l"(c));
    return d;
}
__device__ __forceinline__ uint64_t bcast2(float v) {
    uint64_t d; asm("mov.b64 %0, {%1, %1};" : "=l"(d) : "f"(v)); return d;
}
__device__ __forceinline__ uint64_t pack2(float lo, float hi) {
    uint64_t d; asm("mov.b64 %0, {%1, %2};" : "=l"(d) : "f"(lo), "f"(hi)); return d;
}
__device__ __forceinline__ void unpack2(uint64_t v, float& lo, float& hi) {
    asm("mov.b64 {%0, %1}, %2;" : "=f"(lo), "=f"(hi) : "l"(v));
}

#define THREADS 512

// Dynamic SMEM arena (bytes):
//   h1p  f32[16][16][18]      @     0 (18432)  pooled L1, padded border
//   U8   f32[8][49][16]       @ 18432 (25088)  winograd-domain tiles, 8-ic chunk
//                                               (aliased by h2s f32[1568] later)
//   w2t  u64[16ic][8kq][32oc] @ 43520 (32768)  G w G^T, k-pair packed
//   xs   f32[900]             @ 76288 ( 3600)  30x30 zero-padded input
//   w1p  u64[72]              @ 79888 (  576)
//   b1p  u64[8]               @ 80464 (   64)
//   b2s  f32[32]              @ 80528 (  128)
#define OFF_H1P 0
#define OFF_U   18432
#define OFF_W2T 43520
#define OFF_XS  76288
#define OFF_W1P 79888
#define OFF_B1P 80464
#define OFF_B2  80528
#define SMEM_BYTES 80672

__global__ __launch_bounds__(THREADS, 1) void fused_cnn_kernel(
    const float* __restrict__ x,     // [B,1,28,28]
    const float* __restrict__ w1,    // [16,1,3,3]
    const float* __restrict__ b1,    // [16]
    const float* __restrict__ w2,    // [32,16,3,3]
    const float* __restrict__ b2,    // [32]
    const float* __restrict__ fcw,   // [10,1568]
    const float* __restrict__ fcb,   // [10]
    float* __restrict__ out)         // [B,10]
{
    extern __shared__ __align__(16) unsigned char smraw[];
    float*    h1p = reinterpret_cast<float*>(smraw + OFF_H1P);   // [(ic*16+r)*18 + c]
    float*    U8  = reinterpret_cast<float*>(smraw + OFF_U);     // [(icl*49+tile)*16 + k]
    float*    h2s = U8;                                           // alias after winograd
    uint64_t* w2t = reinterpret_cast<uint64_t*>(smraw + OFF_W2T); // [(ic*8+kq)*32 + oc]
    float*    xs  = reinterpret_cast<float*>(smraw + OFF_XS);
    uint64_t* w1p = reinterpret_cast<uint64_t*>(smraw + OFF_W1P);
    uint64_t* b1p = reinterpret_cast<uint64_t*>(smraw + OFF_B1P);
    float*    b2s = reinterpret_cast<float*>(smraw + OFF_B2);

    const int b    = blockIdx.x;
    const int tid  = threadIdx.x;
    const int wid  = tid >> 5;
    const int lane = tid & 31;          // == output channel in winograd stage
    const float* xb = x + b * 784;

    // ---- Stage 0: stage input, pack layer-1 weights, winograd-transform layer-2 weights ----
    for (int i = tid; i < 900; i += THREADS) {
        int r = i / 30, c = i % 30;
        float v = 0.f;
        if (r >= 1 && r <= 28 && c >= 1 && c <= 28)
            v = xb[(r - 1) * 28 + (c - 1)];
        xs[i] = v;
    }
    for (int i = tid; i < 4608; i += THREADS) h1p[i] = 0.f;
    // w2t: thread (oc, ic) computes T = G g G^T (4x4) for its 3x3 kernel.
    {
        const int ic = tid & 15, oc = tid >> 4;   // 512 = 32 oc x 16 ic
        const float* g = w2 + oc * 144 + ic * 9;
        float g0 = g[0], g1 = g[1], g2 = g[2];
        float g3 = g[3], g4 = g[4], g5 = g[5];
        float g6 = g[6], g7 = g[7], g8 = g[8];
        // Gg rows (4 rows x 3)
        float R[4][3] = {
            { g0, g1, g2 },
            { 0.5f * (g0 + g3 + g6), 0.5f * (g1 + g4 + g7), 0.5f * (g2 + g5 + g8) },
            { 0.5f * (g0 - g3 + g6), 0.5f * (g1 - g4 + g7), 0.5f * (g2 - g5 + g8) },
            { g6, g7, g8 }
        };
        #pragma unroll
        for (int r = 0; r < 4; r++) {
            float a = R[r][0], bb = R[r][1], cc = R[r][2];
            float t0 = a;
            float t1 = 0.5f * (a + bb + cc);
            float t2 = 0.5f * (a - bb + cc);
            float t3 = cc;
            w2t[(ic * 8 + 2 * r) * 32 + oc]     = pack2(t0, t1);
            w2t[(ic * 8 + 2 * r + 1) * 32 + oc] = pack2(t2, t3);
        }
    }
    if (tid < 72) {
        int k = tid / 8, pp = tid % 8;
        w1p[k * 8 + pp] = pack2(w1[(2 * pp) * 9 + k], w1[(2 * pp + 1) * 9 + k]);
    }
    if (tid < 8)  b1p[tid] = pack2(b1[2 * tid], b1[2 * tid + 1]);
    if (tid < 32) b2s[tid] = b2[tid];
    __syncthreads();

    // ---- Stage 1: conv1 + relu + pool2 -> h1p (padded, row stride 18) ----
    if (tid < 392) {
        const int gg  = tid / 196;
        const int pos = tid % 196;
        const int ph = pos / 14, pw = pos % 14;
        const int h = 2 * ph, w = 2 * pw;

        uint64_t winb[16];
        #pragma unroll
        for (int r = 0; r < 4; r++) {
            const float2* row = reinterpret_cast<const float2*>(&xs[(h + r) * 30 + w]);
            float2 a = row[0], c = row[1];
            winb[r * 4 + 0] = bcast2(a.x); winb[r * 4 + 1] = bcast2(a.y);
            winb[r * 4 + 2] = bcast2(c.x); winb[r * 4 + 3] = bcast2(c.y);
        }
        #pragma unroll
        for (int q = 0; q < 4; q++) {
            const int pp = gg * 4 + q;
            uint64_t wk[9];
            #pragma unroll
            for (int k = 0; k < 9; k++) wk[k] = w1p[k * 8 + pp];
            uint64_t acc[4];
            #pragma unroll
            for (int p = 0; p < 4; p++) acc[p] = b1p[pp];
            #pragma unroll
            for (int p = 0; p < 4; p++) {
                const int dy = p >> 1, dx = p & 1;
                #pragma unroll
                for (int kh = 0; kh < 3; kh++)
                    #pragma unroll
                    for (int kw = 0; kw < 3; kw++)
                        acc[p] = fma2(winb[(dy + kh) * 4 + (dx + kw)],
                                      wk[kh * 3 + kw], acc[p]);
            }
            float l0, h0, l1, h1, l2, h2, l3, h3;
            unpack2(acc[0], l0, h0); unpack2(acc[1], l1, h1);
            unpack2(acc[2], l2, h2); unpack2(acc[3], l3, h3);
            float mlo = fmaxf(fmaxf(fmaxf(l0, l1), fmaxf(l2, l3)), 0.f);
            float mhi = fmaxf(fmaxf(fmaxf(h0, h1), fmaxf(h2, h3)), 0.f);
            h1p[((2 * pp) * 16 + ph + 1) * 18 + (pw + 1)]     = mlo;
            h1p[((2 * pp + 1) * 16 + ph + 1) * 18 + (pw + 1)] = mhi;
        }
    }
    __syncthreads();

    // ---- Stage 2: Winograd conv2 + pool2. Warp w owns tiles; lane = oc. ----
    const int nt = (wid == 15) ? 4 : 3;
    int tiles[4];
    tiles[0] = 3 * wid; tiles[1] = 3 * wid + 1; tiles[2] = 3 * wid + 2; tiles[3] = 48;

    uint64_t acc[4][8];
    #pragma unroll
    for (int t = 0; t < 4; t++)
        #pragma unroll
        for (int k = 0; k < 8; k++) acc[t][k] = 0ull;

    for (int c = 0; c < 2; c++) {
        // 2a: transform 8 ics x 49 tiles -> U8 (B^T d B)
        if (tid < 392) {
            const int ic_l = tid / 49;
            const int tile = tid % 49;
            const int ic = c * 8 + ic_l;
            const int ty = tile / 7, tx = tile % 7;
            const float* dp = h1p + (ic * 16 + 2 * ty) * 18 + 2 * tx;
            float d[4][4];
            #pragma unroll
            for (int r = 0; r < 4; r++) {
                float2 e0 = *reinterpret_cast<const float2*>(dp + r * 18);
                float2 e1 = *reinterpret_cast<const float2*>(dp + r * 18 + 2);
                d[r][0] = e0.x; d[r][1] = e0.y; d[r][2] = e1.x; d[r][3] = e1.y;
            }
            float wr[4][4];
            #pragma unroll
            for (int j = 0; j < 4; j++) {
                wr[0][j] = d[0][j] - d[2][j];
                wr[1][j] = d[1][j] + d[2][j];
                wr[2][j] = d[2][j] - d[1][j];
                wr[3][j] = d[1][j] - d[3][j];
            }
            float* up = U8 + (ic_l * 49 + tile) * 16;
            #pragma unroll
            for (int i = 0; i < 4; i++) {
                float4 v;
                v.x = wr[i][0] - wr[i][2];
                v.y = wr[i][1] + wr[i][2];
                v.z = wr[i][2] - wr[i][1];
                v.w = wr[i][1] - wr[i][3];
                *reinterpret_cast<float4*>(up + 4 * i) = v;
            }
        }
        __syncthreads();

        // 2b: elementwise accumulate in transform domain (all 512 threads)
        #pragma unroll
        for (int ic_l = 0; ic_l < 8; ic_l++) {
            const uint64_t* wrow = w2t + ((c * 8 + ic_l) * 8) * 32 + lane;
            uint64_t wk[8];
            #pragma unroll
            for (int kq = 0; kq < 8; kq++) wk[kq] = wrow[kq * 32];
            #pragma unroll
            for (int t = 0; t < 4; t++) {
                if (t < nt) {
                    const ulonglong2* up = reinterpret_cast<const ulonglong2*>(
                        U8 + (ic_l * 49 + tiles[t]) * 16);
                    ulonglong2 a0 = up[0], a1 = up[1], a2 = up[2], a3 = up[3];
                    acc[t][0] = fma2(a0.x, wk[0], acc[t][0]);
                    acc[t][1] = fma2(a0.y, wk[1], acc[t][1]);
                    acc[t][2] = fma2(a1.x, wk[2], acc[t][2]);
                    acc[t][3] = fma2(a1.y, wk[3], acc[t][3]);
                    acc[t][4] = fma2(a2.x, wk[4], acc[t][4]);
                    acc[t][5] = fma2(a2.y, wk[5], acc[t][5]);
                    acc[t][6] = fma2(a3.x, wk[6], acc[t][6]);
                    acc[t][7] = fma2(a3.y, wk[7], acc[t][7]);
                }
            }
        }
        __syncthreads();
    }

    // ---- Inverse transform + bias + pool + relu -> h2s (overwrites U8) ----
    {
        const float bb = b2s[lane];
        #pragma unroll
        for (int t = 0; t < 4; t++) {
            if (t < nt) {
                float m[16];
                #pragma unroll
                for (int r = 0; r < 4; r++) {
                    unpack2(acc[t][2 * r],     m[4 * r + 0], m[4 * r + 1]);
                    unpack2(acc[t][2 * r + 1], m[4 * r + 2], m[4 * r + 3]);
                }
                float p0[4], p1[4];
                #pragma unroll
                for (int cc = 0; cc < 4; cc++) {
                    p0[cc] = m[cc] + m[4 + cc] + m[8 + cc];
                    p1[cc] = m[4 + cc] - m[8 + cc] - m[12 + cc];
                }
                float y00 = p0[0] + p0[1] + p0[2];
                float y01 = p0[1] - p0[2] - p0[3];
                float y10 = p1[0] + p1[1] + p1[2];
                float y11 = p1[1] - p1[2] - p1[3];
                float v = fmaxf(fmaxf(y00, y01), fmaxf(y10, y11)) + bb;
                h2s[lane * 49 + tiles[t]] = fmaxf(v, 0.f);
            }
        }
    }
    __syncthreads();

    // ---- Stage 3: FC 1568 -> 10 (one warp per output) ----
    if (tid < 320) {
        const int o = tid >> 5, l = tid & 31;
        const float* wrow = fcw + o * 1568;
        float s = 0.f;
        #pragma unroll 7
        for (int k = l; k < 1568; k += 32)
            s += h2s[k] * wrow[k];
        #pragma unroll
        for (int off = 16; off; off >>= 1)
            s += __shfl_xor_sync(0xffffffffu, s, off);
        if (l == 0) out[b * 10 + o] = s + fcb[o];
    }
}

extern "C" void kernel_launch(void* const* d_in, const int* in_sizes, int n_in,
                              void* d_out, int out_size) {
    const float* x   = (const float*)d_in[0];
    const float* w1  = (const float*)d_in[1];
    const float* b1  = (const float*)d_in[2];
    const float* w2  = (const float*)d_in[3];
    const float* b2  = (const float*)d_in[4];
    const float* fcw = (const float*)d_in[5];
    const float* fcb = (const float*)d_in[6];
    float* out = (float*)d_out;

    cudaFuncSetAttribute(fused_cnn_kernel,
                         cudaFuncAttributeMaxDynamicSharedMemorySize, SMEM_BYTES);
    const int B = in_sizes[0] / 784;  // 128
    fused_cnn_kernel<<<B, THREADS, SMEM_BYTES>>>(x, w1, b1, w2, b2, fcw, fcb, out);
}